// round 1
// baseline (speedup 1.0000x reference)
#include <cuda_runtime.h>
#include <cuda_bf16.h>

#define T_Q 4096
#define L_KV 4096

// ---------------- scratch (static device globals; no allocation) ----------------
__device__ float g_V[2][L_KV][128];     // projected values, row-major
__device__ float g_kraw[2][L_KV];       // raw key scalar per kv position
__device__ float g_alpha[2][T_Q];
__device__ float g_beta[2][T_Q];
__device__ int   g_a[2][T_Q];           // range start
__device__ int   g_e[2][T_Q];           // effective causal end: [a, e) gets exp weights
__device__ int   g_nc[2][T_Q];          // non-causal in-range count (adds exp(0)=1 each to denom)

// ---------------- kernel 1: per-query params (alpha, beta, ranges) ----------------
__global__ void k_qparams(const float* __restrict__ ref_data, const float* __restrict__ ref_time,
                          const int* __restrict__ ref_idx,
                          const float* __restrict__ m1_time, const int* __restrict__ m1_idx,
                          const float* __restrict__ m2_time, const int* __restrict__ m2_idx,
                          const float* __restrict__ Wq, const float* __restrict__ bq,
                          const float* __restrict__ Wk1, const float* __restrict__ bk1,
                          const float* __restrict__ Wk2, const float* __restrict__ bk2)
{
    int warp = threadIdx.x >> 5, lane = threadIdx.x & 31;
    int t = blockIdx.x * 4 + warp;
    if (t >= T_Q) return;

    // qproj = ref_data[t] @ Wq + bq ; lane owns dims [4*lane, 4*lane+4)
    const float4* Wq4 = (const float4*)Wq;
    float4 acc = make_float4(0.f, 0.f, 0.f, 0.f);
    const float* r = ref_data + t * 64;
    #pragma unroll 8
    for (int i = 0; i < 64; i++) {
        float rv = __ldg(r + i);
        float4 w = __ldg(&Wq4[i * 32 + lane]);
        acc.x += rv * w.x; acc.y += rv * w.y; acc.z += rv * w.z; acc.w += rv * w.w;
    }
    float4 b4 = __ldg(&((const float4*)bq)[lane]);
    float qp[4] = {acc.x + b4.x, acc.y + b4.y, acc.z + b4.z, acc.w + b4.w};
    float qp0 = __shfl_sync(0xffffffffu, qp[0], 0);   // qproj[0]

    // s(t,l) = alpha - beta * kraw,  cq[i] = qproj[i+1] (i<127), cq[127] = 1
    #pragma unroll
    for (int m = 0; m < 2; m++) {
        const float* Wk = m ? Wk2 : Wk1;
        const float* bk = m ? bk2 : bk1;
        float sW = 0.f, sb = 0.f;
        #pragma unroll
        for (int k = 0; k < 4; k++) {
            int d = 4 * lane + k;
            if (d >= 1) { sW += qp[k] * __ldg(Wk + d - 1); sb += qp[k] * __ldg(bk + d - 1); }
        }
        #pragma unroll
        for (int off = 16; off; off >>= 1) {
            sW += __shfl_xor_sync(0xffffffffu, sW, off);
            sb += __shfl_xor_sync(0xffffffffu, sb, off);
        }
        if (lane == 0) {
            g_beta[m][t]  = sW + __ldg(Wk + 127);
            g_alpha[m][t] = qp0 - (sb + __ldg(bk + 127));
        }
    }

    if (lane == 0) {
        int   id = ref_idx[t];
        float qt = ref_time[t];
        #pragma unroll
        for (int m = 0; m < 2; m++) {
            const int*   midx = m ? m2_idx  : m1_idx;
            const float* mt   = m ? m2_time : m1_time;
            int lo, hi, md;
            // lower bound of id
            lo = 0; hi = L_KV;
            while (lo < hi) { md = (lo + hi) >> 1; if (midx[md] < id) lo = md + 1; else hi = md; }
            int a = lo;
            // upper bound of id
            hi = L_KV;
            while (lo < hi) { md = (lo + hi) >> 1; if (midx[md] <= id) lo = md + 1; else hi = md; }
            int b = lo;
            // causal cutoff: first index with kv_time > qt  (causal == kvt <= qt)
            lo = 0; hi = L_KV;
            while (lo < hi) { md = (lo + hi) >> 1; if (mt[md] <= qt) lo = md + 1; else hi = md; }
            int c = lo;
            if (a == b) { a = 0; b = L_KV; }  // fully masked -> safe = 0 everywhere
            int e = min(b, max(c, a));
            g_a[m][t] = a; g_e[m][t] = e; g_nc[m][t] = b - e;
        }
    }
}

// ---------------- kernel 2: V projection + kraw ----------------
__global__ void k_vproj(const float* __restrict__ m1_data, const float* __restrict__ m2_data,
                        const float* __restrict__ Wv1, const float* __restrict__ bv1,
                        const float* __restrict__ Wv2, const float* __restrict__ bv2)
{
    int warp = threadIdx.x >> 5, lane = threadIdx.x & 31;
    int l = blockIdx.x * 4 + warp;
    int m = blockIdx.y;
    if (l >= L_KV) return;

    const float* src = m ? (m2_data + l * 66) : (m1_data + l * 130);
    const float4* Wv4 = (const float4*)(m ? Wv2 : Wv1);
    const float* bv = m ? bv2 : bv1;
    int K = m ? 64 : 128;

    float4 acc = make_float4(0.f, 0.f, 0.f, 0.f);
    #pragma unroll 8
    for (int i = 0; i < K; i++) {
        float rv = __ldg(src + i);
        float4 w = __ldg(&Wv4[i * 32 + lane]);
        acc.x += rv * w.x; acc.y += rv * w.y; acc.z += rv * w.z; acc.w += rv * w.w;
    }
    float4 b4 = __ldg(&((const float4*)bv)[lane]);
    acc.x += b4.x; acc.y += b4.y; acc.z += b4.z; acc.w += b4.w;
    ((float4*)g_V[m][l])[lane] = acc;
    if (lane == 0) g_kraw[m][l] = src[m ? 65 : 129];
}

// ---------------- kernel 3: attention ----------------
// warp = 8 consecutive queries; lane owns 4 output dims (float4 of V row).
// No online max needed: causal logits <= 0, non-causal logits == 0.
__global__ void __launch_bounds__(128) k_attn(const float* __restrict__ lt1,
                                              const float* __restrict__ lt2,
                                              float* __restrict__ out)
{
    int m = blockIdx.y;
    int c = blockIdx.x;
    int qcta = (c & 1) ? (127 - (c >> 1)) : (c >> 1);   // front/back pairing for balance
    int warp = threadIdx.x >> 5, lane = threadIdx.x & 31;
    int t0 = qcta * 32 + warp * 8;

    __shared__ float wbuf[4][8][32];
    float* wme = &wbuf[warp][0][0];

    float itau = __expf(-(m ? *lt2 : *lt1));  // 1/tau

    float alpha[8], beta[8], dpart[8];
    int a[8], e[8], nc[8];
    float4 acc[8];
    int amin = 1 << 30, emax = 0;
    #pragma unroll
    for (int q = 0; q < 8; q++) {
        int t = t0 + q;
        alpha[q] = g_alpha[m][t]; beta[q] = g_beta[m][t];
        a[q] = g_a[m][t]; e[q] = g_e[m][t]; nc[q] = g_nc[m][t];
        dpart[q] = 0.f; acc[q] = make_float4(0.f, 0.f, 0.f, 0.f);
        amin = min(amin, a[q]); emax = max(emax, e[q]);
    }

    const float4* V4 = (const float4*)g_V[m];
    const float* kr = g_kraw[m];

    for (int l0 = amin; l0 < emax; l0 += 32) {
        int l = l0 + lane;
        bool valid = l < emax;
        float k = valid ? kr[l] : 0.f;
        #pragma unroll
        for (int q = 0; q < 8; q++) {
            float s = alpha[q] - beta[q] * k;
            float w = (valid && l >= a[q] && l < e[q]) ? __expf(-s * s * itau) : 0.f;
            wme[q * 32 + lane] = w;
            dpart[q] += w;
        }
        __syncwarp();
        int jmax = min(32, emax - l0);
        #pragma unroll 4
        for (int j = 0; j < jmax; j++) {
            float4 v = V4[(l0 + j) * 32 + lane];
            #pragma unroll
            for (int q = 0; q < 8; q++) {
                float w = wme[q * 32 + j];
                acc[q].x += w * v.x; acc[q].y += w * v.y;
                acc[q].z += w * v.z; acc[q].w += w * v.w;
            }
        }
        __syncwarp();
    }

    #pragma unroll
    for (int q = 0; q < 8; q++)
        #pragma unroll
        for (int off = 16; off; off >>= 1)
            dpart[q] += __shfl_xor_sync(0xffffffffu, dpart[q], off);

    float4* out4 = (float4*)out;
    #pragma unroll
    for (int q = 0; q < 8; q++) {
        float inv = 1.f / (dpart[q] + (float)nc[q]);
        float4 o = make_float4(acc[q].x * inv, acc[q].y * inv, acc[q].z * inv, acc[q].w * inv);
        out4[(t0 + q) * 64 + m * 32 + lane] = o;   // out[t, m*128 + 4*lane .. +3]
    }
}

// ---------------- launch ----------------
extern "C" void kernel_launch(void* const* d_in, const int* in_sizes, int n_in,
                              void* d_out, int out_size)
{
    // Two plausible input orders; disambiguate via m1_data's unique size (4096*130).
    int RD, RT, RI, M1D, M1T, M1I, M2D, M2T, M2I, WQ, BQ, WK1, BK1, WV1, BV1, WK2, BK2, WV2, BV2, LT1, LT2;
    if (in_sizes[3] == 4096 * 130) {
        // setup_inputs dict order
        RD=0; RT=1; RI=2; M1D=3; M1T=4; M1I=5; M2D=6; M2T=7; M2I=8;
        WQ=9; BQ=10; WK1=11; BK1=12; WV1=13; BV1=14; WK2=15; BK2=16; WV2=17; BV2=18; LT1=19; LT2=20;
    } else {
        // reference() signature order
        RD=0; RT=1; M1D=2; M1T=3; M2D=4; M2T=5;
        WQ=6; BQ=7; WK1=8; BK1=9; WV1=10; BV1=11; WK2=12; BK2=13; WV2=14; BV2=15;
        LT1=16; LT2=17; RI=18; M1I=19; M2I=20;
    }

    k_qparams<<<T_Q / 4, 128>>>(
        (const float*)d_in[RD], (const float*)d_in[RT], (const int*)d_in[RI],
        (const float*)d_in[M1T], (const int*)d_in[M1I],
        (const float*)d_in[M2T], (const int*)d_in[M2I],
        (const float*)d_in[WQ], (const float*)d_in[BQ],
        (const float*)d_in[WK1], (const float*)d_in[BK1],
        (const float*)d_in[WK2], (const float*)d_in[BK2]);

    k_vproj<<<dim3(L_KV / 4, 2), 128>>>(
        (const float*)d_in[M1D], (const float*)d_in[M2D],
        (const float*)d_in[WV1], (const float*)d_in[BV1],
        (const float*)d_in[WV2], (const float*)d_in[BV2]);

    k_attn<<<dim3(128, 2), 128>>>(
        (const float*)d_in[LT1], (const float*)d_in[LT2], (float*)d_out);
}

// round 3
// speedup vs baseline: 1.3427x; 1.3427x over previous
#include <cuda_runtime.h>
#include <cuda_bf16.h>

#define T_Q 4096
#define L_KV 4096
#define LPAD (L_KV + 32)
#define NQB 64

typedef unsigned long long ull;

// ---------------- scratch ----------------
__device__ float g_V[2][LPAD][128];
__device__ float g_kraw[2][LPAD];
__device__ float g_alpha[2][T_Q];
__device__ float g_beta[2][T_Q];
__device__ int   g_a[2][T_Q];
__device__ int   g_e[2][T_Q];
__device__ int   g_nc[2][T_Q];

// ---------------- packed f32x2 helpers ----------------
__device__ __forceinline__ ull d_pk2(float a) {
    ull r; asm("mov.b64 %0, {%1, %1};" : "=l"(r) : "f"(a)); return r;
}
__device__ __forceinline__ ull d_fma2(ull a, ull b, ull c) {
    ull d; asm("fma.rn.f32x2 %0, %1, %2, %3;" : "=l"(d) : "l"(a), "l"(b), "l"(c)); return d;
}
__device__ __forceinline__ float2 d_up(ull v) {
    float2 f; asm("mov.b64 {%0, %1}, %2;" : "=f"(f.x), "=f"(f.y) : "l"(v)); return f;
}

// ---------------- kernel 1: fused qparams + vproj ----------------
// blocks [0, NQB): per-query alpha/beta/ranges (64 queries each)
// blocks [NQB, NQB+128): V projection, 64 rows each (m = (b-NQB)>>6)
__global__ void __launch_bounds__(256) k_pre(
    const float* __restrict__ ref_data, const float* __restrict__ ref_time,
    const int* __restrict__ ref_idx,
    const float* __restrict__ m1_data, const float* __restrict__ m1_time, const int* __restrict__ m1_idx,
    const float* __restrict__ m2_data, const float* __restrict__ m2_time, const int* __restrict__ m2_idx,
    const float* __restrict__ Wq, const float* __restrict__ bq,
    const float* __restrict__ Wk1, const float* __restrict__ bk1,
    const float* __restrict__ Wv1, const float* __restrict__ bv1,
    const float* __restrict__ Wk2, const float* __restrict__ bk2,
    const float* __restrict__ Wv2, const float* __restrict__ bv2)
{
    __shared__ __align__(16) float sm[64 * 130];   // 33.3 KB, unioned between paths
    int b = blockIdx.x;
    int tid = threadIdx.x;

    if (b < NQB) {
        // ---- qab path ----
        float* rbuf = sm;                 // [64][65]
        float* wA   = sm + 64 * 65;       // [2][64]
        float* wB   = wA + 128;           // [2][64]
        float* cAB  = wB + 128;           // [4]: cA0 cA1 cB0 cB1
        int*   lb   = (int*)(cAB + 4);    // [2][9]

        int t0 = b * 64;
        for (int i = tid; i < 64 * 64; i += 256) {
            int row = i >> 6, col = i & 63;
            rbuf[row * 65 + col] = ref_data[t0 * 64 + i];
        }

        if (tid < 128) {
            int m = tid >> 6, j = tid & 63;
            const float* Wk = m ? Wk2 : Wk1;
            const float* bk = m ? bk2 : bk1;
            const float* wqrow = Wq + j * 128;
            float aA = 0.f, aB = 0.f;
            #pragma unroll 4
            for (int i = 0; i < 127; i++) {
                float w = __ldg(wqrow + i + 1);
                aA += w * __ldg(bk + i);
                aB += w * __ldg(Wk + i);
            }
            wA[m * 64 + j] = __ldg(wqrow) - aA;
            wB[m * 64 + j] = aB;
        } else if (tid < 146) {
            int s = tid - 128, m = s / 9, g = s % 9;
            const int* midx = m ? m2_idx : m1_idx;
            int lo = 0, hi = L_KV;
            while (lo < hi) {
                int md = (lo + hi) >> 1;
                if (midx[md] < g) lo = md + 1; else hi = md;
            }
            lb[m * 9 + g] = lo;
        } else if (tid < 150) {
            int s = tid - 146;           // 0:cA0 1:cA1 2:cB0 3:cB1
            int m = s & 1; bool isB = s >= 2;
            const float* Wk = m ? Wk2 : Wk1;
            const float* bk = m ? bk2 : bk1;
            const float* vec = isB ? Wk : bk;
            float acc = 0.f;
            for (int i = 0; i < 127; i++) acc += __ldg(bq + i + 1) * __ldg(vec + i);
            cAB[s] = isB ? (acc + __ldg(Wk + 127)) : (__ldg(bq) - acc - __ldg(bk + 127));
        }
        __syncthreads();

        if (tid < 64) {
            int t = t0 + tid;
            float d0 = 0.f, d1 = 0.f, d2 = 0.f, d3 = 0.f;
            #pragma unroll 8
            for (int i = 0; i < 64; i++) {
                float r = rbuf[tid * 65 + i];
                d0 += r * wA[i];       d1 += r * wB[i];
                d2 += r * wA[64 + i];  d3 += r * wB[64 + i];
            }
            g_alpha[0][t] = d0 + cAB[0]; g_beta[0][t] = d1 + cAB[2];
            g_alpha[1][t] = d2 + cAB[1]; g_beta[1][t] = d3 + cAB[3];

            int id = ref_idx[t];
            float qt = ref_time[t];
            // two independent binary-search chains, each predicated (keeps ILP)
            int lo1 = 0, hi1 = L_KV, lo2 = 0, hi2 = L_KV;
            #pragma unroll 1
            for (int it = 0; it < 13; it++) {
                if (lo1 < hi1) {
                    int md1 = (lo1 + hi1) >> 1;
                    if (m1_time[md1] <= qt) lo1 = md1 + 1; else hi1 = md1;
                }
                if (lo2 < hi2) {
                    int md2 = (lo2 + hi2) >> 1;
                    if (m2_time[md2] <= qt) lo2 = md2 + 1; else hi2 = md2;
                }
            }
            {
                int a = lb[id], bb = lb[id + 1];
                if (a == bb) { a = 0; bb = L_KV; }
                int e = min(bb, max(lo1, a));
                g_a[0][t] = a; g_e[0][t] = e; g_nc[0][t] = bb - e;
            }
            {
                int a = lb[9 + id], bb = lb[9 + id + 1];
                if (a == bb) { a = 0; bb = L_KV; }
                int e = min(bb, max(lo2, a));
                g_a[1][t] = a; g_e[1][t] = e; g_nc[1][t] = bb - e;
            }
        }
        return;
    }

    // ---- vproj path ----
    int vb = b - NQB;            // 0..127
    int m = vb >> 6;
    int rb = vb & 63;
    int stride = m ? 66 : 130;
    int K      = m ? 64 : 128;
    const float* src = (m ? m2_data : m1_data) + rb * 64 * stride;

    for (int i = tid; i < 64 * stride; i += 256) sm[i] = src[i];

    if (vb == 0) {   // zero the padding rows once per launch (before attn)
        float* gv = &g_V[0][0][0];
        for (int i = tid; i < 2 * 32 * 128; i += 256) {
            int mm = i / (32 * 128);
            int r  = i - mm * 32 * 128;
            gv[(mm * LPAD + L_KV) * 128 + r] = 0.f;
        }
        if (tid < 64) g_kraw[tid >> 5][L_KV + (tid & 31)] = 0.f;
    }
    __syncthreads();

    int w = tid >> 5, lane = tid & 31;
    const ulonglong2* Wv2p = (const ulonglong2*)(m ? Wv2 : Wv1);
    float4 bias = ((const float4*)(m ? bv2 : bv1))[lane];
    const float* rows = sm + (w * 8) * stride;

    ull alo[8], ahi[8];
    #pragma unroll
    for (int q = 0; q < 8; q++) { alo[q] = 0ull; ahi[q] = 0ull; }

    #pragma unroll 4
    for (int i = 0; i < K; i++) {
        ulonglong2 wv = Wv2p[i * 32 + lane];
        #pragma unroll
        for (int q = 0; q < 8; q++) {
            ull rv = d_pk2(rows[q * stride + i]);
            alo[q] = d_fma2(rv, wv.x, alo[q]);
            ahi[q] = d_fma2(rv, wv.y, ahi[q]);
        }
    }

    int r0 = rb * 64 + w * 8;
    #pragma unroll
    for (int q = 0; q < 8; q++) {
        float2 lo = d_up(alo[q]), hi = d_up(ahi[q]);
        float4 o = make_float4(lo.x + bias.x, lo.y + bias.y, hi.x + bias.z, hi.y + bias.w);
        ((float4*)g_V[m][r0 + q])[lane] = o;
    }
    if (lane < 8) g_kraw[m][r0 + lane] = sm[(w * 8 + lane) * stride + stride - 1];
}

// ---------------- kernel 2: attention ----------------
// CTA = 2 warps, each warp 8 consecutive queries; lane owns 4 output dims.
// Causal logits <= 0, non-causal contribute exp(0)=1 -> no online max needed.
__global__ void __launch_bounds__(64) k_attn(const float* __restrict__ lt1,
                                             const float* __restrict__ lt2,
                                             float* __restrict__ out)
{
    int m = blockIdx.y;
    int c = blockIdx.x;                              // 0..255
    int oc = (c & 1) ? (255 - (c >> 1)) : (c >> 1);  // front/back pairing for balance
    int warp = threadIdx.x >> 5, lane = threadIdx.x & 31;
    int t0 = (oc * 2 + warp) * 8;

    __shared__ __align__(16) ull wsm[2][8][32];
    ull* wme = &wsm[warp][0][0];

    float nitau = -__expf(-(m ? *lt2 : *lt1));       // -1/tau

    float alpha[8], nbeta[8], dpart[8];
    int a[8], e[8], nc[8];
    ull alo[8], ahi[8];
    int amin = 1 << 30, emax = 0;
    #pragma unroll
    for (int q = 0; q < 8; q++) {
        int t = t0 + q;
        alpha[q] = g_alpha[m][t]; nbeta[q] = -g_beta[m][t];
        a[q] = g_a[m][t]; e[q] = g_e[m][t]; nc[q] = g_nc[m][t];
        dpart[q] = 0.f; alo[q] = 0ull; ahi[q] = 0ull;
        amin = min(amin, a[q]); emax = max(emax, e[q]);
    }

    const ulonglong2* V2 = (const ulonglong2*)g_V[m];
    const float* kr = g_kraw[m];

    for (int l0 = amin; l0 < emax; l0 += 32) {
        int l = l0 + lane;
        float k = kr[l];                              // padded; zero weight outside [a,e)
        #pragma unroll
        for (int q = 0; q < 8; q++) {
            float s = fmaf(nbeta[q], k, alpha[q]);
            float w = (l >= a[q] && l < e[q]) ? __expf(s * s * nitau) : 0.f;
            wme[q * 32 + lane] = d_pk2(w);
            dpart[q] += w;
        }
        __syncwarp();
        #pragma unroll 8
        for (int j = 0; j < 32; j++) {
            ulonglong2 v = V2[(l0 + j) * 32 + lane];  // pad rows are zeroed
            #pragma unroll
            for (int q = 0; q < 8; q++) {
                ull wq = wme[q * 32 + j];
                alo[q] = d_fma2(wq, v.x, alo[q]);
                ahi[q] = d_fma2(wq, v.y, ahi[q]);
            }
        }
        __syncwarp();
    }

    #pragma unroll
    for (int q = 0; q < 8; q++)
        #pragma unroll
        for (int off = 16; off; off >>= 1)
            dpart[q] += __shfl_xor_sync(0xffffffffu, dpart[q], off);

    float4* out4 = (float4*)out;
    #pragma unroll
    for (int q = 0; q < 8; q++) {
        float inv = 1.f / (dpart[q] + (float)nc[q]);
        float2 lo = d_up(alo[q]), hi = d_up(ahi[q]);
        float4 o = make_float4(lo.x * inv, lo.y * inv, hi.x * inv, hi.y * inv);
        out4[(t0 + q) * 64 + m * 32 + lane] = o;
    }
}

// ---------------- launch ----------------
extern "C" void kernel_launch(void* const* d_in, const int* in_sizes, int n_in,
                              void* d_out, int out_size)
{
    int RD, RT, RI, M1D, M1T, M1I, M2D, M2T, M2I, WQ, BQ, WK1, BK1, WV1, BV1, WK2, BK2, WV2, BV2, LT1, LT2;
    if (in_sizes[3] == 4096 * 130) {
        RD=0; RT=1; RI=2; M1D=3; M1T=4; M1I=5; M2D=6; M2T=7; M2I=8;
        WQ=9; BQ=10; WK1=11; BK1=12; WV1=13; BV1=14; WK2=15; BK2=16; WV2=17; BV2=18; LT1=19; LT2=20;
    } else {
        RD=0; RT=1; M1D=2; M1T=3; M2D=4; M2T=5;
        WQ=6; BQ=7; WK1=8; BK1=9; WV1=10; BV1=11; WK2=12; BK2=13; WV2=14; BV2=15;
        LT1=16; LT2=17; RI=18; M1I=19; M2I=20;
    }

    k_pre<<<NQB + 128, 256>>>(
        (const float*)d_in[RD], (const float*)d_in[RT], (const int*)d_in[RI],
        (const float*)d_in[M1D], (const float*)d_in[M1T], (const int*)d_in[M1I],
        (const float*)d_in[M2D], (const float*)d_in[M2T], (const int*)d_in[M2I],
        (const float*)d_in[WQ], (const float*)d_in[BQ],
        (const float*)d_in[WK1], (const float*)d_in[BK1],
        (const float*)d_in[WV1], (const float*)d_in[BV1],
        (const float*)d_in[WK2], (const float*)d_in[BK2],
        (const float*)d_in[WV2], (const float*)d_in[BV2]);

    k_attn<<<dim3(256, 2), 64>>>(
        (const float*)d_in[LT1], (const float*)d_in[LT2], (float*)d_out);
}

// round 5
// speedup vs baseline: 1.8871x; 1.4054x over previous
#include <cuda_runtime.h>
#include <cuda_bf16.h>

#define T_Q 4096
#define L_KV 4096
#define LPAD (L_KV + 32)
#define NQB 64
#define NCHUNK 2

typedef unsigned long long ull;

// ---------------- scratch ----------------
__device__ float g_V[2][LPAD][128];
__device__ float g_kraw[2][LPAD];
__device__ float g_alpha[2][T_Q];
__device__ float g_beta[2][T_Q];
__device__ int   g_a[2][T_Q];
__device__ int   g_e[2][T_Q];
__device__ int   g_nc[2][T_Q];
__device__ float g_pacc[NCHUNK][2][T_Q][128];
__device__ float g_pden[NCHUNK][2][T_Q];

// ---------------- helpers ----------------
__device__ __forceinline__ ull d_pk2(float a) {
    ull r; asm("mov.b64 %0, {%1, %1};" : "=l"(r) : "f"(a)); return r;
}
__device__ __forceinline__ ull d_fma2(ull a, ull b, ull c) {
    ull d; asm("fma.rn.f32x2 %0, %1, %2, %3;" : "=l"(d) : "l"(a), "l"(b), "l"(c)); return d;
}
__device__ __forceinline__ float2 d_up(ull v) {
    float2 f; asm("mov.b64 {%0, %1}, %2;" : "=f"(f.x), "=f"(f.y) : "l"(v)); return f;
}
__device__ __forceinline__ unsigned d_su32(const void* p) {
    unsigned r;
    asm("{ .reg .u64 t; cvta.to.shared.u64 t, %1; cvt.u32.u64 %0, t; }" : "=r"(r) : "l"(p));
    return r;
}

// ---------------- kernel 1: fused qparams + vproj ----------------
__global__ void __launch_bounds__(256) k_pre(
    const float* __restrict__ ref_data, const float* __restrict__ ref_time,
    const int* __restrict__ ref_idx,
    const float* __restrict__ m1_data, const float* __restrict__ m1_time, const int* __restrict__ m1_idx,
    const float* __restrict__ m2_data, const float* __restrict__ m2_time, const int* __restrict__ m2_idx,
    const float* __restrict__ Wq, const float* __restrict__ bq,
    const float* __restrict__ Wk1, const float* __restrict__ bk1,
    const float* __restrict__ Wv1, const float* __restrict__ bv1,
    const float* __restrict__ Wk2, const float* __restrict__ bk2,
    const float* __restrict__ Wv2, const float* __restrict__ bv2)
{
    __shared__ __align__(16) float sm[64 * 130];
    int b = blockIdx.x;
    int tid = threadIdx.x;

    if (b < NQB) {
        float* rbuf = sm;
        float* wA   = sm + 64 * 65;
        float* wB   = wA + 128;
        float* cAB  = wB + 128;
        int*   lb   = (int*)(cAB + 4);

        int t0 = b * 64;
        for (int i = tid; i < 64 * 64; i += 256) {
            int row = i >> 6, col = i & 63;
            rbuf[row * 65 + col] = ref_data[t0 * 64 + i];
        }

        if (tid < 128) {
            int m = tid >> 6, j = tid & 63;
            const float* Wk = m ? Wk2 : Wk1;
            const float* bk = m ? bk2 : bk1;
            const float* wqrow = Wq + j * 128;
            float aA = 0.f, aB = 0.f;
            #pragma unroll 4
            for (int i = 0; i < 127; i++) {
                float w = __ldg(wqrow + i + 1);
                aA += w * __ldg(bk + i);
                aB += w * __ldg(Wk + i);
            }
            wA[m * 64 + j] = __ldg(wqrow) - aA;
            wB[m * 64 + j] = aB;
        } else if (tid < 146) {
            int s = tid - 128, m = s / 9, g = s % 9;
            const int* midx = m ? m2_idx : m1_idx;
            int lo = 0, hi = L_KV;
            while (lo < hi) {
                int md = (lo + hi) >> 1;
                if (midx[md] < g) lo = md + 1; else hi = md;
            }
            lb[m * 9 + g] = lo;
        } else if (tid < 150) {
            int s = tid - 146;
            int m = s & 1; bool isB = s >= 2;
            const float* Wk = m ? Wk2 : Wk1;
            const float* bk = m ? bk2 : bk1;
            const float* vec = isB ? Wk : bk;
            float acc = 0.f;
            for (int i = 0; i < 127; i++) acc += __ldg(bq + i + 1) * __ldg(vec + i);
            cAB[s] = isB ? (acc + __ldg(Wk + 127)) : (__ldg(bq) - acc - __ldg(bk + 127));
        }
        __syncthreads();

        if (tid < 64) {
            int t = t0 + tid;
            float d0 = 0.f, d1 = 0.f, d2 = 0.f, d3 = 0.f;
            #pragma unroll 8
            for (int i = 0; i < 64; i++) {
                float r = rbuf[tid * 65 + i];
                d0 += r * wA[i];       d1 += r * wB[i];
                d2 += r * wA[64 + i];  d3 += r * wB[64 + i];
            }
            g_alpha[0][t] = d0 + cAB[0]; g_beta[0][t] = d1 + cAB[2];
            g_alpha[1][t] = d2 + cAB[1]; g_beta[1][t] = d3 + cAB[3];

            int id = ref_idx[t];
            float qt = ref_time[t];
            int lo1 = 0, hi1 = L_KV, lo2 = 0, hi2 = L_KV;
            #pragma unroll 1
            for (int it = 0; it < 13; it++) {
                if (lo1 < hi1) {
                    int md1 = (lo1 + hi1) >> 1;
                    if (m1_time[md1] <= qt) lo1 = md1 + 1; else hi1 = md1;
                }
                if (lo2 < hi2) {
                    int md2 = (lo2 + hi2) >> 1;
                    if (m2_time[md2] <= qt) lo2 = md2 + 1; else hi2 = md2;
                }
            }
            {
                int a = lb[id], bb = lb[id + 1];
                if (a == bb) { a = 0; bb = L_KV; }
                int e = min(bb, max(lo1, a));
                g_a[0][t] = a; g_e[0][t] = e; g_nc[0][t] = bb - e;
            }
            {
                int a = lb[9 + id], bb = lb[9 + id + 1];
                if (a == bb) { a = 0; bb = L_KV; }
                int e = min(bb, max(lo2, a));
                g_a[1][t] = a; g_e[1][t] = e; g_nc[1][t] = bb - e;
            }
        }
        return;
    }

    // ---- vproj path ----
    int vb = b - NQB;
    int m = vb >> 6;
    int rb = vb & 63;
    int stride = m ? 66 : 130;
    int K      = m ? 64 : 128;
    const float* src = (m ? m2_data : m1_data) + rb * 64 * stride;

    for (int i = tid; i < 64 * stride; i += 256) sm[i] = src[i];

    if (vb == 0) {
        float* gv = &g_V[0][0][0];
        for (int i = tid; i < 2 * 32 * 128; i += 256) {
            int mm = i / (32 * 128);
            int r  = i - mm * 32 * 128;
            gv[(mm * LPAD + L_KV) * 128 + r] = 0.f;
        }
        if (tid < 64) g_kraw[tid >> 5][L_KV + (tid & 31)] = 0.f;
    }
    __syncthreads();

    int w = tid >> 5, lane = tid & 31;
    const ulonglong2* Wv2p = (const ulonglong2*)(m ? Wv2 : Wv1);
    float4 bias = ((const float4*)(m ? bv2 : bv1))[lane];
    const float* rows = sm + (w * 8) * stride;

    ull alo[8], ahi[8];
    #pragma unroll
    for (int q = 0; q < 8; q++) { alo[q] = 0ull; ahi[q] = 0ull; }

    #pragma unroll 4
    for (int i = 0; i < K; i++) {
        ulonglong2 wv = Wv2p[i * 32 + lane];
        #pragma unroll
        for (int q = 0; q < 8; q++) {
            ull rv = d_pk2(rows[q * stride + i]);
            alo[q] = d_fma2(rv, wv.x, alo[q]);
            ahi[q] = d_fma2(rv, wv.y, ahi[q]);
        }
    }

    int r0 = rb * 64 + w * 8;
    #pragma unroll
    for (int q = 0; q < 8; q++) {
        float2 lo = d_up(alo[q]), hi = d_up(ahi[q]);
        float4 o = make_float4(lo.x + bias.x, lo.y + bias.y, hi.x + bias.z, hi.y + bias.w);
        ((float4*)g_V[m][r0 + q])[lane] = o;
    }
    if (lane < 8) g_kraw[m][r0 + lane] = sm[(w * 8 + lane) * stride + stride - 1];
}

// ---------------- kernel 2: attention (smem-staged, cp.async double buffer, L-chunked) ----------------
__global__ void __launch_bounds__(128) k_attn(const float* __restrict__ lt1,
                                              const float* __restrict__ lt2)
{
    int m = blockIdx.y, ch = blockIdx.z;
    int c = blockIdx.x;                              // 0..127
    int qb = (c & 1) ? (127 - (c >> 1)) : (c >> 1);  // front/back pairing for balance
    int tid = threadIdx.x;
    int warp = tid >> 5, lane = tid & 31;
    int t0c = qb * 32;

    __shared__ __align__(16) float buf[2][32 * 128];   // 32 KB
    __shared__ __align__(16) ull wsm[4][8][32];        // 8 KB
    __shared__ int s_c0[32], s_c1[32], s_b[2];

    if (tid < 32) {
        int t = t0c + tid;
        int a = g_a[m][t], e = g_e[m][t];
        int len = e - a;
        int c0 = a + ((len * ch) >> 1);
        int c1 = a + ((len * (ch + 1)) >> 1);
        s_c0[tid] = c0; s_c1[tid] = c1;
        int rmin = (c1 > c0) ? c0 : 0x7fffffff;
        int rmax = (c1 > c0) ? c1 : 0;
        #pragma unroll
        for (int off = 16; off; off >>= 1) {
            rmin = min(rmin, __shfl_xor_sync(0xffffffffu, rmin, off));
            rmax = max(rmax, __shfl_xor_sync(0xffffffffu, rmax, off));
        }
        if (tid == 0) { s_b[0] = rmin; s_b[1] = rmax; }
    }
    __syncthreads();
    int amin = s_b[0], emax = s_b[1];

    float nitau = -__expf(-(m ? *lt2 : *lt1));       // -1/tau
    int t0 = t0c + warp * 8;

    float alpha[8], nbeta[8], dpart[8];
    int aq[8], eq[8];
    ull alo[8], ahi[8];
    #pragma unroll
    for (int q = 0; q < 8; q++) {
        int t = t0 + q;
        alpha[q] = g_alpha[m][t]; nbeta[q] = -g_beta[m][t];
        aq[q] = s_c0[warp * 8 + q]; eq[q] = s_c1[warp * 8 + q];
        dpart[q] = 0.f; alo[q] = 0ull; ahi[q] = 0ull;
    }

    const float* gV = &g_V[m][0][0];
    const float* kr = g_kraw[m];
    ull* wme = &wsm[warp][0][0];
    unsigned sbuf0 = d_su32(&buf[0][0]);
    unsigned sbuf1 = d_su32(&buf[1][0]);

    int ntiles = (emax > amin) ? ((emax - amin + 31) >> 5) : 0;

    if (ntiles > 0) {
        {
            const float* g = gV + (size_t)amin * 128;
            #pragma unroll
            for (int i = 0; i < 8; i++) {
                int cid = i * 128 + tid;
                asm volatile("cp.async.cg.shared.global [%0], [%1], 16;"
                             :: "r"(sbuf0 + cid * 16), "l"(g + cid * 4) : "memory");
            }
            asm volatile("cp.async.commit_group;" ::: "memory");
        }
        int p = 0;
        for (int it = 0; it < ntiles; it++) {
            int l0 = amin + it * 32;
            asm volatile("cp.async.wait_group 0;" ::: "memory");
            __syncthreads();
            if (it + 1 < ntiles) {
                const float* g = gV + (size_t)(l0 + 32) * 128;
                unsigned sd = p ? sbuf0 : sbuf1;
                #pragma unroll
                for (int i = 0; i < 8; i++) {
                    int cid = i * 128 + tid;
                    asm volatile("cp.async.cg.shared.global [%0], [%1], 16;"
                                 :: "r"(sd + cid * 16), "l"(g + cid * 4) : "memory");
                }
            }
            asm volatile("cp.async.commit_group;" ::: "memory");

            // weight phase: lane = row
            int l = l0 + lane;
            float k = __ldg(kr + l);
            #pragma unroll
            for (int q = 0; q < 8; q++) {
                float s = fmaf(nbeta[q], k, alpha[q]);
                float w = (l >= aq[q] && l < eq[q]) ? __expf(s * s * nitau) : 0.f;
                wme[q * 32 + lane] = d_pk2(w);
                dpart[q] += w;
            }
            __syncwarp();

            // compute phase from smem tile
            const ulonglong2* bp = (const ulonglong2*)buf[p];
            #pragma unroll 8
            for (int j = 0; j < 32; j++) {
                ulonglong2 v = bp[j * 32 + lane];
                #pragma unroll
                for (int q = 0; q < 8; q++) {
                    ull wq = wme[q * 32 + j];
                    alo[q] = d_fma2(wq, v.x, alo[q]);
                    ahi[q] = d_fma2(wq, v.y, ahi[q]);
                }
            }
            p ^= 1;
        }
    }

    #pragma unroll
    for (int q = 0; q < 8; q++)
        #pragma unroll
        for (int off = 16; off; off >>= 1)
            dpart[q] += __shfl_xor_sync(0xffffffffu, dpart[q], off);

    float4* pa = (float4*)g_pacc[ch][m];
    #pragma unroll
    for (int q = 0; q < 8; q++) {
        float2 lo = d_up(alo[q]), hi = d_up(ahi[q]);
        pa[(t0 + q) * 32 + lane] = make_float4(lo.x, lo.y, hi.x, hi.y);
        if (lane == 0) g_pden[ch][m][t0 + q] = dpart[q];
    }
}

// ---------------- kernel 3: combine chunks + normalize ----------------
__global__ void __launch_bounds__(256) k_norm(float* __restrict__ out)
{
    int idx = blockIdx.x * 256 + threadIdx.x;        // 0 .. 2*4096*32-1
    int m = idx >> 17;
    int r = idx & 131071;
    int t = r >> 5, lane = r & 31;

    float4 a0 = ((const float4*)g_pacc[0][m])[t * 32 + lane];
    float4 a1 = ((const float4*)g_pacc[1][m])[t * 32 + lane];
    float den = g_pden[0][m][t] + g_pden[1][m][t] + (float)g_nc[m][t];
    float inv = 1.f / den;
    ((float4*)out)[t * 64 + m * 32 + lane] =
        make_float4((a0.x + a1.x) * inv, (a0.y + a1.y) * inv,
                    (a0.z + a1.z) * inv, (a0.w + a1.w) * inv);
}

// ---------------- launch ----------------
extern "C" void kernel_launch(void* const* d_in, const int* in_sizes, int n_in,
                              void* d_out, int out_size)
{
    int RD, RT, RI, M1D, M1T, M1I, M2D, M2T, M2I, WQ, BQ, WK1, BK1, WV1, BV1, WK2, BK2, WV2, BV2, LT1, LT2;
    if (in_sizes[3] == 4096 * 130) {
        RD=0; RT=1; RI=2; M1D=3; M1T=4; M1I=5; M2D=6; M2T=7; M2I=8;
        WQ=9; BQ=10; WK1=11; BK1=12; WV1=13; BV1=14; WK2=15; BK2=16; WV2=17; BV2=18; LT1=19; LT2=20;
    } else {
        RD=0; RT=1; M1D=2; M1T=3; M2D=4; M2T=5;
        WQ=6; BQ=7; WK1=8; BK1=9; WV1=10; BV1=11; WK2=12; BK2=13; WV2=14; BV2=15;
        LT1=16; LT2=17; RI=18; M1I=19; M2I=20;
    }

    k_pre<<<NQB + 128, 256>>>(
        (const float*)d_in[RD], (const float*)d_in[RT], (const int*)d_in[RI],
        (const float*)d_in[M1D], (const float*)d_in[M1T], (const int*)d_in[M1I],
        (const float*)d_in[M2D], (const float*)d_in[M2T], (const int*)d_in[M2I],
        (const float*)d_in[WQ], (const float*)d_in[BQ],
        (const float*)d_in[WK1], (const float*)d_in[BK1],
        (const float*)d_in[WV1], (const float*)d_in[BV1],
        (const float*)d_in[WK2], (const float*)d_in[BK2],
        (const float*)d_in[WV2], (const float*)d_in[BV2]);

    k_attn<<<dim3(128, 2, NCHUNK), 128>>>(
        (const float*)d_in[LT1], (const float*)d_in[LT2]);

    k_norm<<<(2 * T_Q * 32) / 256, 256>>>((float*)d_out);
}